// round 2
// baseline (speedup 1.0000x reference)
#include <cuda_runtime.h>
#include <math.h>

// Problem constants
#define Bn 16
#define Cn 96
#define Hn 128
#define Wn 128
#define HWn (Hn*Wn)

// ---------------- scratch (static device arrays; no allocation) ----------------
__device__ float g_flow [Bn*2*HWn];          // upflow output
__device__ float g_feat2[Bn*Cn*HWn];         // warped features
__device__ float g_corr [Bn*56*HWn];         // lrelu(corr), padded 49->56 channels
__device__ float g_x1   [Bn*128*HWn];
__device__ float g_x2   [Bn*64*HWn];
__device__ float g_x3   [Bn*32*HWn];
__device__ float g_w1p  [128*56*9];          // w1 padded to 56 input channels

// ---------------- f32x2 helpers (sm_103a packed fp32) ----------------
__device__ __forceinline__ unsigned long long pack2(float lo, float hi) {
    unsigned long long r;
    asm("mov.b64 %0, {%1, %2};" : "=l"(r)
        : "r"(__float_as_uint(lo)), "r"(__float_as_uint(hi)));
    return r;
}
__device__ __forceinline__ void unpack2(unsigned long long v, float& lo, float& hi) {
    unsigned a, b;
    asm("mov.b64 {%0, %1}, %2;" : "=r"(a), "=r"(b) : "l"(v));
    lo = __uint_as_float(a); hi = __uint_as_float(b);
}
__device__ __forceinline__ unsigned long long fma2(unsigned long long a,
                                                   unsigned long long b,
                                                   unsigned long long c) {
    unsigned long long d;
    asm("fma.rn.f32x2 %0, %1, %2, %3;" : "=l"(d) : "l"(a), "l"(b), "l"(c));
    return d;
}

// ---------------- 1) upflow: transposed conv, groups=2, k=4, stride=2, pad≡2 ----------------
__global__ void upflow_k(const float* __restrict__ flowIn, const float* __restrict__ wu) {
    int idx = blockIdx.x * 256 + threadIdx.x;  // B*2*H*W = 524288
    int x = idx & 127;
    int y = (idx >> 7) & 127;
    int c = (idx >> 14) & 1;
    int b = idx >> 15;
    float acc = 0.f;
#pragma unroll
    for (int ky = 0; ky < 4; ky++) {
        int tyy = y + ky - 2;
        if (tyy & 1) continue;
        int iy = tyy >> 1;
        if (iy < 0 || iy >= 64) continue;
#pragma unroll
        for (int kx = 0; kx < 4; kx++) {
            int txx = x + kx - 2;
            if (txx & 1) continue;
            int ix = txx >> 1;
            if (ix < 0 || ix >= 64) continue;
            // wf = flip(wu) -> wf[ky][kx] = wu[3-ky][3-kx]
            acc += wu[c * 16 + (3 - ky) * 4 + (3 - kx)] *
                   flowIn[((b * 2 + c) * 64 + iy) * 64 + ix];
        }
    }
    g_flow[idx] = acc;
}

// ---------------- 2) backward warp (bilinear, zeros padding, validity mask) ----------------
__global__ void warp_k(const float* __restrict__ feat) {
    int x = threadIdx.x;
    int y = blockIdx.x;
    int b = blockIdx.y;
    int pp = y * Wn + x;
    float sx = (float)x + 2.5f * g_flow[(b * 2 + 0) * HWn + pp];
    float sy = (float)y + 2.5f * g_flow[(b * 2 + 1) * HWn + pp];
    float x0f = floorf(sx), y0f = floorf(sy);
    float ax = sx - x0f, ay = sy - y0f;
    int ix0 = (int)x0f, iy0 = (int)y0f;
    int ix1 = ix0 + 1, iy1 = iy0 + 1;
    bool vx0 = (ix0 >= 0) && (ix0 < Wn);
    bool vx1 = (ix1 >= 0) && (ix1 < Wn);
    bool vy0 = (iy0 >= 0) && (iy0 < Hn);
    bool vy1 = (iy1 >= 0) && (iy1 < Hn);
    float wa = (1.f - ax) * (1.f - ay);
    float wb = ax * (1.f - ay);
    float wc = (1.f - ax) * ay;
    float wd = ax * ay;
    bool va = vx0 && vy0, vb = vx1 && vy0, vc = vx0 && vy1, vd = vx1 && vy1;
    float alpha = (va ? wa : 0.f) + (vb ? wb : 0.f) + (vc ? wc : 0.f) + (vd ? wd : 0.f);
    float* outb = g_feat2 + (size_t)b * Cn * HWn + pp;
    if (alpha > 0.999f) {
        const float* inb = feat + (size_t)b * Cn * HWn;
        int oa = iy0 * Wn + ix0, ob = iy0 * Wn + ix1;
        int oc_ = iy1 * Wn + ix0, od = iy1 * Wn + ix1;
        for (int c = 0; c < Cn; c++) {
            const float* pl = inb + c * HWn;
            float v = 0.f;
            if (va) v += wa * pl[oa];
            if (vb) v += wb * pl[ob];
            if (vc) v += wc * pl[oc_];
            if (vd) v += wd * pl[od];
            outb[c * HWn] = v;
        }
    } else {
        for (int c = 0; c < Cn; c++) outb[c * HWn] = 0.f;
    }
}

// ---------------- 3) correlation (7x7 displacements, mean over 96 ch) + lrelu ----------------
__global__ __launch_bounds__(256) void corr_k(const float* __restrict__ first) {
    __shared__ float sF[4][16][16];
    __shared__ float sS[4][22][23];
    int tid = threadIdx.x;
    int tx = tid & 15, ty = tid >> 4;
    int x0 = blockIdx.x * 16, y0 = blockIdx.y * 16, b = blockIdx.z;
    float acc[49];
#pragma unroll
    for (int d = 0; d < 49; d++) acc[d] = 0.f;
    const float* fb = first + (size_t)b * Cn * HWn;
    const float* sb = g_feat2 + (size_t)b * Cn * HWn;
    for (int cb = 0; cb < 24; cb++) {
        __syncthreads();
#pragma unroll
        for (int q = 0; q < 4; q++)
            sF[q][ty][tx] = fb[(cb * 4 + q) * HWn + (y0 + ty) * Wn + x0 + tx];
        for (int e = tid; e < 4 * 22 * 22; e += 256) {
            int q = e / 484, r = e % 484, ry = r / 22, rx = r % 22;
            int gy = y0 + ry - 3, gx = x0 + rx - 3;
            float v = 0.f;
            if (gy >= 0 && gy < Hn && gx >= 0 && gx < Wn)
                v = sb[(cb * 4 + q) * HWn + gy * Wn + gx];
            sS[q][ry][rx] = v;
        }
        __syncthreads();
#pragma unroll
        for (int q = 0; q < 4; q++) {
            float f = sF[q][ty][tx];
#pragma unroll
            for (int dy = 0; dy < 7; dy++)
#pragma unroll
                for (int dx = 0; dx < 7; dx++)
                    acc[dy * 7 + dx] += f * sS[q][ty + dy][tx + dx];
        }
    }
    int op = (y0 + ty) * Wn + x0 + tx;
    float* ob = g_corr + (size_t)b * 56 * HWn + op;
#pragma unroll
    for (int d = 0; d < 49; d++) {
        float v = acc[d] * (1.f / 96.f);
        ob[d * HWn] = (v >= 0.f) ? v : 0.1f * v;
    }
#pragma unroll
    for (int d = 49; d < 56; d++) ob[d * HWn] = 0.f;
}

// ---------------- pad w1 (49 -> 56 input channels) ----------------
__global__ void prep_w1(const float* __restrict__ w1) {
    int idx = blockIdx.x * 256 + threadIdx.x;
    if (idx >= 128 * 56 * 9) return;
    int co = idx / (56 * 9);
    int r = idx % (56 * 9);
    int ci = r / 9, k = r % 9;
    g_w1p[idx] = (ci < 49) ? w1[(co * 49 + ci) * 9 + k] : 0.f;
}

// ---------------- 4) conv3x3 + optional lrelu, f32x2 FMA ----------------
// Block: 16x16 spatial tile x 16 output channels. 256 threads.
// Thread: 2 adjacent x-pixels (one f32x2 lane-pair) x 8 output channels.
template <int CI, int CO, bool RELU>
__global__ __launch_bounds__(256) void conv3_k(const float* __restrict__ in,
                                               const float* __restrict__ wgt,
                                               const float* __restrict__ bias,
                                               float* __restrict__ out) {
    __shared__ float sIn[8][18][20];
    __shared__ unsigned long long sW[16][8][9];  // duplicated (w,w) pairs
    int tid = threadIdx.x;
    int z = blockIdx.z;
    int b = z / (CO / 16);
    int coBase = (z % (CO / 16)) * 16;
    int x0 = blockIdx.x * 16, y0 = blockIdx.y * 16;
    int pairId = tid & 127;
    int coHalf = tid >> 7;        // 0 or 1 -> which 8 output channels
    int py = pairId >> 3;         // 0..15
    int px = (pairId & 7) * 2;    // 0,2,...,14
    unsigned long long acc[8];
#pragma unroll
    for (int i = 0; i < 8; i++) acc[i] = 0ULL;

    for (int cb = 0; cb < CI / 8; cb++) {
        __syncthreads();
        // input tile with 1-halo, zero-padded
        for (int e = tid; e < 8 * 18 * 18; e += 256) {
            int ci = e / 324, r = e % 324, ry = r / 18, rx = r % 18;
            int gy = y0 + ry - 1, gx = x0 + rx - 1;
            float v = 0.f;
            if (gy >= 0 && gy < Hn && gx >= 0 && gx < Wn)
                v = in[(((size_t)b * CI + cb * 8 + ci) * Hn + gy) * Wn + gx];
            sIn[ci][ry][rx] = v;
        }
        // weights for 16 co x 8 ci x 9, duplicated into 64-bit pairs
        for (int e = tid; e < 16 * 8 * 9; e += 256) {
            int co = e / 72, r = e % 72, ci = r / 9, k = r % 9;
            unsigned u = __float_as_uint(wgt[((coBase + co) * CI + cb * 8 + ci) * 9 + k]);
            sW[co][ci][k] = ((unsigned long long)u << 32) | (unsigned long long)u;
        }
        __syncthreads();
#pragma unroll
        for (int ci = 0; ci < 8; ci++) {
            float v[3][4];
#pragma unroll
            for (int ky = 0; ky < 3; ky++)
#pragma unroll
                for (int j = 0; j < 4; j++)
                    v[ky][j] = sIn[ci][py + ky][px + j];
            unsigned long long p[3][3];
#pragma unroll
            for (int ky = 0; ky < 3; ky++)
#pragma unroll
                for (int kx = 0; kx < 3; kx++)
                    p[ky][kx] = pack2(v[ky][kx], v[ky][kx + 1]);
#pragma unroll
            for (int co = 0; co < 8; co++) {
                const unsigned long long* wp = &sW[coHalf * 8 + co][ci][0];
#pragma unroll
                for (int k = 0; k < 9; k++)
                    acc[co] = fma2(wp[k], p[k / 3][k % 3], acc[co]);
            }
        }
    }
    int yy = y0 + py, xx = x0 + px;
#pragma unroll
    for (int co = 0; co < 8; co++) {
        int oc = coBase + coHalf * 8 + co;
        float lo, hi;
        unpack2(acc[co], lo, hi);
        float bv = bias[oc];
        lo += bv; hi += bv;
        if (RELU) {
            lo = (lo >= 0.f) ? lo : 0.1f * lo;
            hi = (hi >= 0.f) ? hi : 0.1f * hi;
        }
        float2* op = (float2*)&out[(((size_t)b * CO + oc) * Hn + yy) * Wn + xx];
        *op = make_float2(lo, hi);
    }
}

// ---------------- 5) conv5x5 (32->2, pad 2) + flow add -> final output ----------------
__global__ __launch_bounds__(256) void conv5_k(const float* __restrict__ w4,
                                               const float* __restrict__ b4,
                                               float* __restrict__ out) {
    __shared__ float sIn[4][20][20];
    __shared__ float sW[1600];  // 2 * 32 * 25
    int tid = threadIdx.x;
    int tx = tid & 15, ty = tid >> 4;
    int x0 = blockIdx.x * 16, y0 = blockIdx.y * 16, b = blockIdx.z;
    for (int e = tid; e < 1600; e += 256) sW[e] = w4[e];
    float a0 = 0.f, a1 = 0.f;
    for (int cb = 0; cb < 8; cb++) {
        __syncthreads();
        for (int e = tid; e < 4 * 20 * 20; e += 256) {
            int ci = e / 400, r = e % 400, ry = r / 20, rx = r % 20;
            int gy = y0 + ry - 2, gx = x0 + rx - 2;
            float v = 0.f;
            if (gy >= 0 && gy < Hn && gx >= 0 && gx < Wn)
                v = g_x3[(((size_t)b * 32 + cb * 4 + ci) * Hn + gy) * Wn + gx];
            sIn[ci][ry][rx] = v;
        }
        __syncthreads();
#pragma unroll
        for (int ci = 0; ci < 4; ci++) {
            int cig = cb * 4 + ci;
#pragma unroll
            for (int ky = 0; ky < 5; ky++)
#pragma unroll
                for (int kx = 0; kx < 5; kx++) {
                    float v = sIn[ci][ty + ky][tx + kx];
                    a0 += sW[cig * 25 + ky * 5 + kx] * v;
                    a1 += sW[(32 + cig) * 25 + ky * 5 + kx] * v;
                }
        }
    }
    int p = (y0 + ty) * Wn + x0 + tx;
    out[(b * 2 + 0) * HWn + p] = a0 + b4[0] + g_flow[(b * 2 + 0) * HWn + p];
    out[(b * 2 + 1) * HWn + p] = a1 + b4[1] + g_flow[(b * 2 + 1) * HWn + p];
}

// ---------------- launch ----------------
extern "C" void kernel_launch(void* const* d_in, const int* in_sizes, int n_in,
                              void* d_out, int out_size) {
    // Input order: tensorFirst, tensorSecond, tensorFeaturesFirst, tensorFeaturesSecond,
    //              tensorFlow, wu, w1, b1, w2, b2, w3, b3, w4, b4
    const float* featFirst  = (const float*)d_in[2];
    const float* featSecond = (const float*)d_in[3];
    const float* flowIn     = (const float*)d_in[4];
    const float* wu = (const float*)d_in[5];
    const float* w1 = (const float*)d_in[6];
    const float* b1 = (const float*)d_in[7];
    const float* w2 = (const float*)d_in[8];
    const float* b2 = (const float*)d_in[9];
    const float* w3 = (const float*)d_in[10];
    const float* b3 = (const float*)d_in[11];
    const float* w4 = (const float*)d_in[12];
    const float* b4 = (const float*)d_in[13];
    float* out = (float*)d_out;

    float *p_corr, *p_x1, *p_x2, *p_x3, *p_w1p;
    cudaGetSymbolAddress((void**)&p_corr, g_corr);
    cudaGetSymbolAddress((void**)&p_x1, g_x1);
    cudaGetSymbolAddress((void**)&p_x2, g_x2);
    cudaGetSymbolAddress((void**)&p_x3, g_x3);
    cudaGetSymbolAddress((void**)&p_w1p, g_w1p);

    prep_w1<<<(128 * 56 * 9 + 255) / 256, 256>>>(w1);
    upflow_k<<<(Bn * 2 * HWn) / 256, 256>>>(flowIn, wu);
    warp_k<<<dim3(Hn, Bn), Wn>>>(featSecond);
    corr_k<<<dim3(8, 8, Bn), 256>>>(featFirst);
    conv3_k<56, 128, true><<<dim3(8, 8, Bn * 8), 256>>>(p_corr, p_w1p, b1, p_x1);
    conv3_k<128, 64, true><<<dim3(8, 8, Bn * 4), 256>>>(p_x1, w2, b2, p_x2);
    conv3_k<64, 32, true><<<dim3(8, 8, Bn * 2), 256>>>(p_x2, w3, b3, p_x3);
    conv5_k<<<dim3(8, 8, Bn), 256>>>(w4, b4, out);
}

// round 3
// speedup vs baseline: 1.2222x; 1.2222x over previous
#include <cuda_runtime.h>
#include <math.h>

// Problem constants
#define Bn 16
#define Cn 96
#define Hn 128
#define Wn 128
#define HWn (Hn*Wn)

typedef unsigned long long ull;

// ---------------- scratch (static device arrays; no allocation) ----------------
__device__ float g_flow [Bn*2*HWn];          // upflow output
__device__ float g_feat2[Bn*Cn*HWn];         // warped features
__device__ float g_corr [Bn*56*HWn];         // lrelu(corr), padded 49->56 channels
__device__ float g_x1   [Bn*128*HWn];
__device__ float g_x2   [Bn*64*HWn];
__device__ float g_x3   [Bn*32*HWn];
__device__ float g_w1p  [128*56*9];          // w1 padded to 56 input channels

// ---------------- f32x2 helpers (sm_103a packed fp32) ----------------
__device__ __forceinline__ void unpack2(ull v, float& lo, float& hi) {
    unsigned a, b;
    asm("mov.b64 {%0, %1}, %2;" : "=r"(a), "=r"(b) : "l"(v));
    lo = __uint_as_float(a); hi = __uint_as_float(b);
}
__device__ __forceinline__ ull fma2(ull a, ull b, ull c) {
    ull d;
    asm("fma.rn.f32x2 %0, %1, %2, %3;" : "=l"(d) : "l"(a), "l"(b), "l"(c));
    return d;
}
// (a.hi, b.lo) -> one f32x2  : builds odd-offset pairs from two even-aligned pairs
__device__ __forceinline__ ull mixp(ull a, ull b) {
    ull r;
    asm("{\n\t"
        ".reg .b32 al, ah, bl, bh;\n\t"
        "mov.b64 {al, ah}, %1;\n\t"
        "mov.b64 {bl, bh}, %2;\n\t"
        "mov.b64 %0, {ah, bl};\n\t"
        "}" : "=l"(r) : "l"(a), "l"(b));
    return r;
}

// ---------------- 1) upflow: transposed conv, groups=2, k=4, stride=2, pad≡2 ----------------
__global__ void upflow_k(const float* __restrict__ flowIn, const float* __restrict__ wu) {
    int idx = blockIdx.x * 256 + threadIdx.x;  // B*2*H*W = 524288
    int x = idx & 127;
    int y = (idx >> 7) & 127;
    int c = (idx >> 14) & 1;
    int b = idx >> 15;
    float acc = 0.f;
#pragma unroll
    for (int ky = 0; ky < 4; ky++) {
        int tyy = y + ky - 2;
        if (tyy & 1) continue;
        int iy = tyy >> 1;
        if (iy < 0 || iy >= 64) continue;
#pragma unroll
        for (int kx = 0; kx < 4; kx++) {
            int txx = x + kx - 2;
            if (txx & 1) continue;
            int ix = txx >> 1;
            if (ix < 0 || ix >= 64) continue;
            acc += wu[c * 16 + (3 - ky) * 4 + (3 - kx)] *
                   flowIn[((b * 2 + c) * 64 + iy) * 64 + ix];
        }
    }
    g_flow[idx] = acc;
}

// ---------------- 2) backward warp (bilinear, zeros padding, validity mask) ----------------
__global__ void warp_k(const float* __restrict__ feat) {
    int x = threadIdx.x;
    int y = blockIdx.x;
    int b = blockIdx.y;
    int pp = y * Wn + x;
    float sx = (float)x + 2.5f * g_flow[(b * 2 + 0) * HWn + pp];
    float sy = (float)y + 2.5f * g_flow[(b * 2 + 1) * HWn + pp];
    float x0f = floorf(sx), y0f = floorf(sy);
    float ax = sx - x0f, ay = sy - y0f;
    int ix0 = (int)x0f, iy0 = (int)y0f;
    int ix1 = ix0 + 1, iy1 = iy0 + 1;
    bool vx0 = (ix0 >= 0) && (ix0 < Wn);
    bool vx1 = (ix1 >= 0) && (ix1 < Wn);
    bool vy0 = (iy0 >= 0) && (iy0 < Hn);
    bool vy1 = (iy1 >= 0) && (iy1 < Hn);
    float wa = (1.f - ax) * (1.f - ay);
    float wb = ax * (1.f - ay);
    float wc = (1.f - ax) * ay;
    float wd = ax * ay;
    bool va = vx0 && vy0, vb = vx1 && vy0, vc = vx0 && vy1, vd = vx1 && vy1;
    float alpha = (va ? wa : 0.f) + (vb ? wb : 0.f) + (vc ? wc : 0.f) + (vd ? wd : 0.f);
    float* outb = g_feat2 + (size_t)b * Cn * HWn + pp;
    if (alpha > 0.999f) {
        const float* inb = feat + (size_t)b * Cn * HWn;
        int oa = iy0 * Wn + ix0, ob = iy0 * Wn + ix1;
        int oc_ = iy1 * Wn + ix0, od = iy1 * Wn + ix1;
        for (int c = 0; c < Cn; c++) {
            const float* pl = inb + c * HWn;
            float v = 0.f;
            if (va) v += wa * pl[oa];
            if (vb) v += wb * pl[ob];
            if (vc) v += wc * pl[oc_];
            if (vd) v += wd * pl[od];
            outb[c * HWn] = v;
        }
    } else {
        for (int c = 0; c < Cn; c++) outb[c * HWn] = 0.f;
    }
}

// ---------------- 3) correlation (7x7 displacements, mean over 96 ch) + lrelu ----------------
// Tile 32x x 16y, 256 threads, each thread = x-pair via f32x2. 49 f32x2 accumulators.
__global__ __launch_bounds__(256) void corr_k(const float* __restrict__ first) {
    __shared__ __align__(16) float sS[4][22][40];
    int tid = threadIdx.x;
    int tx2 = (tid & 15) * 2;     // 0..30
    int ty  = tid >> 4;           // 0..15
    int x0 = blockIdx.x * 32, y0 = blockIdx.y * 16, b = blockIdx.z;
    ull acc[49];
#pragma unroll
    for (int d = 0; d < 49; d++) acc[d] = 0ULL;
    const float* fb = first  + (size_t)b * Cn * HWn;
    const float* sb = g_feat2 + (size_t)b * Cn * HWn;

    for (int cb = 0; cb < 24; cb++) {
        __syncthreads();
        for (int e = tid; e < 4 * 22 * 38; e += 256) {
            int q = e / 836, r = e % 836, ry = r / 38, rx = r % 38;
            int gy = y0 + ry - 3, gx = x0 + rx - 3;
            float v = 0.f;
            if (gy >= 0 && gy < Hn && gx >= 0 && gx < Wn)
                v = sb[(cb * 4 + q) * HWn + gy * Wn + gx];
            sS[q][ry][rx] = v;
        }
        __syncthreads();
#pragma unroll
        for (int q = 0; q < 4; q++) {
            // first-feature pair straight from global (coalesced LDG.64)
            ull f2 = *(const ull*)&fb[(cb * 4 + q) * HWn + (y0 + ty) * Wn + x0 + tx2];
#pragma unroll
            for (int dy = 0; dy < 7; dy++) {
                const float* rp = &sS[q][ty + dy][tx2];
                ull E0 = *(const ull*)(rp + 0);
                ull E1 = *(const ull*)(rp + 2);
                ull E2 = *(const ull*)(rp + 4);
                ull E3 = *(const ull*)(rp + 6);
                ull O0 = mixp(E0, E1);
                ull O1 = mixp(E1, E2);
                ull O2 = mixp(E2, E3);
                ull* a = &acc[dy * 7];
                a[0] = fma2(f2, E0, a[0]);
                a[1] = fma2(f2, O0, a[1]);
                a[2] = fma2(f2, E1, a[2]);
                a[3] = fma2(f2, O1, a[3]);
                a[4] = fma2(f2, E2, a[4]);
                a[5] = fma2(f2, O2, a[5]);
                a[6] = fma2(f2, E3, a[6]);
            }
        }
    }
    int op = (y0 + ty) * Wn + x0 + tx2;
    float* ob = g_corr + (size_t)b * 56 * HWn + op;
#pragma unroll
    for (int d = 0; d < 49; d++) {
        float lo, hi;
        unpack2(acc[d], lo, hi);
        lo *= (1.f / 96.f); hi *= (1.f / 96.f);
        lo = (lo >= 0.f) ? lo : 0.1f * lo;
        hi = (hi >= 0.f) ? hi : 0.1f * hi;
        *(float2*)&ob[d * HWn] = make_float2(lo, hi);
    }
#pragma unroll
    for (int d = 49; d < 56; d++)
        *(float2*)&ob[d * HWn] = make_float2(0.f, 0.f);
}

// ---------------- pad w1 (49 -> 56 input channels) ----------------
__global__ void prep_w1(const float* __restrict__ w1) {
    int idx = blockIdx.x * 256 + threadIdx.x;
    if (idx >= 128 * 56 * 9) return;
    int co = idx / (56 * 9);
    int r = idx % (56 * 9);
    int ci = r / 9, k = r % 9;
    g_w1p[idx] = (ci < 49) ? w1[(co * 49 + ci) * 9 + k] : 0.f;
}

// ---------------- 4) conv3x3 + optional lrelu, register-blocked f32x2 ----------------
// Block: 32x x 16y spatial tile x 16 output channels, 256 threads (8 warps).
// Warp = one co-pair (2 output channels); lane = 4 x-groups x 8 y-groups.
// Thread: 2 rows x 8 x-pixels (4 f32x2) x 2 co -> 16 f32x2 accumulators.
// Weights hoisted to registers per ci (broadcast LDS.64, reused over 72 FMA2).
template <int CI, int CO, bool RELU>
__global__ __launch_bounds__(256) void conv3_k(const float* __restrict__ in,
                                               const float* __restrict__ wgt,
                                               const float* __restrict__ bias,
                                               float* __restrict__ out) {
    __shared__ __align__(16) float sIn[8][18][38];   // 8 ci x (16+2) rows x (32+2 used, 38 stride)
    __shared__ __align__(16) ull   sW[16][8][9];     // duplicated (w,w) pairs
    int tid = threadIdx.x;
    int lane = tid & 31;
    int wrp  = tid >> 5;          // 0..7 -> co pair
    int g = lane & 3;             // x-group
    int r = lane >> 2;            // y-group
    int px = g * 8;               // 0,8,16,24
    int py = r * 2;               // 0,2,...,14
    int coL = wrp * 2;

    int z = blockIdx.z;
    int b = z / (CO / 16);
    int coBase = (z % (CO / 16)) * 16;
    int x0 = blockIdx.x * 32, y0 = blockIdx.y * 16;

    ull acc[2][2][4];             // [co2][row2][pair]
#pragma unroll
    for (int i = 0; i < 2; i++)
#pragma unroll
        for (int j = 0; j < 2; j++)
#pragma unroll
            for (int k = 0; k < 4; k++) acc[i][j][k] = 0ULL;

    for (int cb = 0; cb < CI / 8; cb++) {
        __syncthreads();
        // input tile with 1-halo, zero-padded (34 used cols, stride 38)
        for (int e = tid; e < 8 * 18 * 34; e += 256) {
            int ci = e / 612, rm = e % 612, ry = rm / 34, rx = rm % 34;
            int gy = y0 + ry - 1, gx = x0 + rx - 1;
            float v = 0.f;
            if (gy >= 0 && gy < Hn && gx >= 0 && gx < Wn)
                v = in[(((size_t)b * CI + cb * 8 + ci) * Hn + gy) * Wn + gx];
            sIn[ci][ry][rx] = v;
        }
        // weights for 16 co x 8 ci x 9, duplicated into 64-bit pairs
        for (int e = tid; e < 16 * 8 * 9; e += 256) {
            int co = e / 72, rm = e % 72, ci = rm / 9, k = rm % 9;
            unsigned u = __float_as_uint(wgt[((coBase + co) * CI + cb * 8 + ci) * 9 + k]);
            sW[co][ci][k] = ((ull)u << 32) | (ull)u;
        }
        __syncthreads();
#pragma unroll
        for (int ci = 0; ci < 8; ci++) {
            ull w[2][9];
#pragma unroll
            for (int c2 = 0; c2 < 2; c2++)
#pragma unroll
                for (int k = 0; k < 9; k++)
                    w[c2][k] = sW[coL + c2][ci][k];   // warp-broadcast LDS.64
#pragma unroll
            for (int ri = 0; ri < 4; ri++) {          // stream input rows py..py+3
                const float* rp = &sIn[ci][py + ri][px];
                ull E[5], O[4];
#pragma unroll
                for (int j = 0; j < 5; j++) E[j] = *(const ull*)(rp + 2 * j);
#pragma unroll
                for (int j = 0; j < 4; j++) O[j] = mixp(E[j], E[j + 1]);
#pragma unroll
                for (int r2 = 0; r2 < 2; r2++) {
                    int ky = ri - r2;
                    if (ky < 0 || ky > 2) continue;   // resolved at compile time
#pragma unroll
                    for (int c2 = 0; c2 < 2; c2++) {
                        ull w0 = w[c2][ky * 3 + 0];
                        ull w1_ = w[c2][ky * 3 + 1];
                        ull w2_ = w[c2][ky * 3 + 2];
#pragma unroll
                        for (int j = 0; j < 4; j++) {
                            ull a = acc[c2][r2][j];
                            a = fma2(w0, E[j], a);
                            a = fma2(w1_, O[j], a);
                            a = fma2(w2_, E[j + 1], a);
                            acc[c2][r2][j] = a;
                        }
                    }
                }
            }
        }
    }
#pragma unroll
    for (int c2 = 0; c2 < 2; c2++) {
        int oc = coBase + coL + c2;
        float bv = bias[oc];
#pragma unroll
        for (int r2 = 0; r2 < 2; r2++) {
            int yy = y0 + py + r2;
#pragma unroll
            for (int j = 0; j < 4; j++) {
                float lo, hi;
                unpack2(acc[c2][r2][j], lo, hi);
                lo += bv; hi += bv;
                if (RELU) {
                    lo = (lo >= 0.f) ? lo : 0.1f * lo;
                    hi = (hi >= 0.f) ? hi : 0.1f * hi;
                }
                int xx = x0 + px + 2 * j;
                *(float2*)&out[(((size_t)b * CO + oc) * Hn + yy) * Wn + xx] =
                    make_float2(lo, hi);
            }
        }
    }
}

// ---------------- 5) conv5x5 (32->2, pad 2) + flow add -> final output ----------------
__global__ __launch_bounds__(256) void conv5_k(const float* __restrict__ w4,
                                               const float* __restrict__ b4,
                                               float* __restrict__ out) {
    __shared__ float sIn[4][20][20];
    __shared__ float sW[1600];  // 2 * 32 * 25
    int tid = threadIdx.x;
    int tx = tid & 15, ty = tid >> 4;
    int x0 = blockIdx.x * 16, y0 = blockIdx.y * 16, b = blockIdx.z;
    for (int e = tid; e < 1600; e += 256) sW[e] = w4[e];
    float a0 = 0.f, a1 = 0.f;
    for (int cb = 0; cb < 8; cb++) {
        __syncthreads();
        for (int e = tid; e < 4 * 20 * 20; e += 256) {
            int ci = e / 400, r = e % 400, ry = r / 20, rx = r % 20;
            int gy = y0 + ry - 2, gx = x0 + rx - 2;
            float v = 0.f;
            if (gy >= 0 && gy < Hn && gx >= 0 && gx < Wn)
                v = g_x3[(((size_t)b * 32 + cb * 4 + ci) * Hn + gy) * Wn + gx];
            sIn[ci][ry][rx] = v;
        }
        __syncthreads();
#pragma unroll
        for (int ci = 0; ci < 4; ci++) {
            int cig = cb * 4 + ci;
#pragma unroll
            for (int ky = 0; ky < 5; ky++)
#pragma unroll
                for (int kx = 0; kx < 5; kx++) {
                    float v = sIn[ci][ty + ky][tx + kx];
                    a0 += sW[cig * 25 + ky * 5 + kx] * v;
                    a1 += sW[(32 + cig) * 25 + ky * 5 + kx] * v;
                }
        }
    }
    int p = (y0 + ty) * Wn + x0 + tx;
    out[(b * 2 + 0) * HWn + p] = a0 + b4[0] + g_flow[(b * 2 + 0) * HWn + p];
    out[(b * 2 + 1) * HWn + p] = a1 + b4[1] + g_flow[(b * 2 + 1) * HWn + p];
}

// ---------------- launch ----------------
extern "C" void kernel_launch(void* const* d_in, const int* in_sizes, int n_in,
                              void* d_out, int out_size) {
    const float* featFirst  = (const float*)d_in[2];
    const float* featSecond = (const float*)d_in[3];
    const float* flowIn     = (const float*)d_in[4];
    const float* wu = (const float*)d_in[5];
    const float* w1 = (const float*)d_in[6];
    const float* b1 = (const float*)d_in[7];
    const float* w2 = (const float*)d_in[8];
    const float* b2 = (const float*)d_in[9];
    const float* w3 = (const float*)d_in[10];
    const float* b3 = (const float*)d_in[11];
    const float* w4 = (const float*)d_in[12];
    const float* b4 = (const float*)d_in[13];
    float* out = (float*)d_out;

    float *p_corr, *p_x1, *p_x2, *p_x3, *p_w1p;
    cudaGetSymbolAddress((void**)&p_corr, g_corr);
    cudaGetSymbolAddress((void**)&p_x1, g_x1);
    cudaGetSymbolAddress((void**)&p_x2, g_x2);
    cudaGetSymbolAddress((void**)&p_x3, g_x3);
    cudaGetSymbolAddress((void**)&p_w1p, g_w1p);

    prep_w1<<<(128 * 56 * 9 + 255) / 256, 256>>>(w1);
    upflow_k<<<(Bn * 2 * HWn) / 256, 256>>>(flowIn, wu);
    warp_k<<<dim3(Hn, Bn), Wn>>>(featSecond);
    corr_k<<<dim3(4, 8, Bn), 256>>>(featFirst);
    conv3_k<56, 128, true><<<dim3(4, 8, Bn * 8), 256>>>(p_corr, p_w1p, b1, p_x1);
    conv3_k<128, 64, true><<<dim3(4, 8, Bn * 4), 256>>>(p_x1, w2, b2, p_x2);
    conv3_k<64, 32, true><<<dim3(4, 8, Bn * 2), 256>>>(p_x2, w3, b3, p_x3);
    conv5_k<<<dim3(8, 8, Bn), 256>>>(w4, b4, out);
}

// round 7
// speedup vs baseline: 1.3699x; 1.1208x over previous
#include <cuda_runtime.h>
#include <math.h>
#include <stdint.h>

// Problem constants
#define Bn 16
#define Cn 96
#define Hn 128
#define Wn 128
#define HWn (Hn*Wn)

#define PSTR 136              // padded row stride (floats)
#define PH1 130               // halo-1 plane rows
#define PH2 134               // halo-3 plane rows (feat2)
#define PH4 132               // halo-2 plane rows (x3)
#define PL1 (PH1*PSTR)
#define PL2 (PH2*PSTR)
#define PL4 (PH4*PSTR)
#define LEAD 64               // leading zero pad (floats) so col -4 reads are in-bounds

typedef unsigned long long ull;

// ---------------- scratch (static device arrays; zero-initialized -> borders stay 0) ----
__device__ float g_flow [Bn*2*HWn];
__device__ float g_feat2[LEAD + Bn*Cn*PL2];       // warped features, halo 3
__device__ float g_corr [LEAD + Bn*56*PL1];       // lrelu(corr), 49 used + 7 zero planes, halo 1
__device__ float g_x1   [LEAD + Bn*128*PL1];
__device__ float g_x2   [LEAD + Bn*64*PL1];
__device__ float g_x3   [LEAD + Bn*32*PL4];       // halo 2
__device__ ull   g_w1d  [8*7*1152];               // duplicated weight pairs
__device__ ull   g_w2d  [4*16*1152];
__device__ ull   g_w3d  [2*8*1152];

// ---------------- f32x2 helpers ----------------
__device__ __forceinline__ void unpack2(ull v, float& lo, float& hi) {
    unsigned a, b;
    asm("mov.b64 {%0, %1}, %2;" : "=r"(a), "=r"(b) : "l"(v));
    lo = __uint_as_float(a); hi = __uint_as_float(b);
}
__device__ __forceinline__ ull fma2(ull a, ull b, ull c) {
    ull d;
    asm("fma.rn.f32x2 %0, %1, %2, %3;" : "=l"(d) : "l"(a), "l"(b), "l"(c));
    return d;
}
__device__ __forceinline__ ull mixp(ull a, ull b) {  // (a.hi, b.lo)
    ull r;
    asm("{\n\t.reg .b32 al, ah, bl, bh;\n\t"
        "mov.b64 {al, ah}, %1;\n\tmov.b64 {bl, bh}, %2;\n\t"
        "mov.b64 %0, {ah, bl};\n\t}" : "=l"(r) : "l"(a), "l"(b));
    return r;
}
// ---------------- cp.async helpers ----------------
__device__ __forceinline__ void cpa16(uint32_t sdst, const void* gsrc) {
    asm volatile("{\n\t.reg .u64 g;\n\tcvta.to.global.u64 g, %1;\n\t"
                 "cp.async.cg.shared.global [%0], [g], 16;\n\t}"
                 :: "r"(sdst), "l"(gsrc) : "memory");
}
__device__ __forceinline__ void cpcommit() { asm volatile("cp.async.commit_group;" ::: "memory"); }
template <int N>
__device__ __forceinline__ void cpwait() { asm volatile("cp.async.wait_group %0;" :: "n"(N) : "memory"); }

// ---------------- 1) upflow ----------------
__global__ void upflow_k(const float* __restrict__ flowIn, const float* __restrict__ wu) {
    int idx = blockIdx.x * 256 + threadIdx.x;
    int x = idx & 127, y = (idx >> 7) & 127, c = (idx >> 14) & 1, b = idx >> 15;
    float acc = 0.f;
#pragma unroll
    for (int ky = 0; ky < 4; ky++) {
        int tyy = y + ky - 2;
        if (tyy & 1) continue;
        int iy = tyy >> 1;
        if (iy < 0 || iy >= 64) continue;
#pragma unroll
        for (int kx = 0; kx < 4; kx++) {
            int txx = x + kx - 2;
            if (txx & 1) continue;
            int ix = txx >> 1;
            if (ix < 0 || ix >= 64) continue;
            acc += wu[c * 16 + (3 - ky) * 4 + (3 - kx)] *
                   flowIn[((b * 2 + c) * 64 + iy) * 64 + ix];
        }
    }
    g_flow[idx] = acc;
}

// ---------------- 2) backward warp -> padded g_feat2 ----------------
__global__ void warp_k(const float* __restrict__ feat) {
    int x = threadIdx.x, y = blockIdx.x, b = blockIdx.y;
    int pp = y * Wn + x;
    float sx = (float)x + 2.5f * g_flow[(b * 2 + 0) * HWn + pp];
    float sy = (float)y + 2.5f * g_flow[(b * 2 + 1) * HWn + pp];
    float x0f = floorf(sx), y0f = floorf(sy);
    float ax = sx - x0f, ay = sy - y0f;
    int ix0 = (int)x0f, iy0 = (int)y0f;
    int ix1 = ix0 + 1, iy1 = iy0 + 1;
    bool vx0 = (ix0 >= 0) && (ix0 < Wn), vx1 = (ix1 >= 0) && (ix1 < Wn);
    bool vy0 = (iy0 >= 0) && (iy0 < Hn), vy1 = (iy1 >= 0) && (iy1 < Hn);
    float wa = (1.f - ax) * (1.f - ay), wb = ax * (1.f - ay);
    float wc = (1.f - ax) * ay,         wd = ax * ay;
    bool va = vx0 && vy0, vb = vx1 && vy0, vc = vx0 && vy1, vd = vx1 && vy1;
    float alpha = (va ? wa : 0.f) + (vb ? wb : 0.f) + (vc ? wc : 0.f) + (vd ? wd : 0.f);
    float* outb = g_feat2 + LEAD + (size_t)b * Cn * PL2 + (y + 3) * PSTR + x;
    if (alpha > 0.999f) {
        const float* inb = feat + (size_t)b * Cn * HWn;
        int oa = iy0 * Wn + ix0, ob = iy0 * Wn + ix1;
        int oc_ = iy1 * Wn + ix0, od = iy1 * Wn + ix1;
#pragma unroll 4
        for (int c = 0; c < Cn; c++) {
            const float* pl = inb + c * HWn;
            float v = 0.f;
            if (va) v += wa * __ldg(pl + oa);
            if (vb) v += wb * __ldg(pl + ob);
            if (vc) v += wc * __ldg(pl + oc_);
            if (vd) v += wd * __ldg(pl + od);
            outb[(size_t)c * PL2] = v;
        }
    } else {
        for (int c = 0; c < Cn; c++) outb[(size_t)c * PL2] = 0.f;
    }
}

// ---------------- 3) correlation + lrelu, cp.async double-buffered ----------------
__global__ __launch_bounds__(256) void corr_k(const float* __restrict__ first) {
    __shared__ __align__(16) float sS[2][4][22][40];
    int tid = threadIdx.x;
    int tx2 = (tid & 15) * 2;     // 0..30
    int ty  = tid >> 4;           // 0..15
    int x0 = blockIdx.x * 32, y0 = blockIdx.y * 16, b = blockIdx.z;
    ull acc[49];
#pragma unroll
    for (int d = 0; d < 49; d++) acc[d] = 0ULL;
    const float* fb  = first + (size_t)b * Cn * HWn;
    const float* sb  = g_feat2 + LEAD + (size_t)b * Cn * PL2;
    uint32_t sbase = (uint32_t)__cvta_generic_to_shared(&sS[0][0][0][0]);

    // issue chunk for cb into buffer d
    auto issue = [&](int cb, int d) {
        for (int e = tid; e < 4 * 22 * 10; e += 256) {
            int q = e / 220, r = e % 220, ry = r / 10, cx = r % 10;
            uint32_t sd = sbase + (((d * 4 + q) * 22 + ry) * 40 + cx * 4) * 4;
            cpa16(sd, sb + (size_t)(cb * 4 + q) * PL2 + (y0 + ry) * PSTR + x0 - 4 + cx * 4);
        }
        cpcommit();
    };
    issue(0, 0);
    for (int cb = 0; cb < 24; cb++) {
        int cur = cb & 1;
        if (cb + 1 < 24) { issue(cb + 1, cur ^ 1); cpwait<1>(); }
        else             { cpwait<0>(); }
        __syncthreads();
#pragma unroll
        for (int q = 0; q < 4; q++) {
            ull f2 = *(const ull*)&fb[(cb * 4 + q) * HWn + (y0 + ty) * Wn + x0 + tx2];
#pragma unroll
            for (int dy = 0; dy < 7; dy++) {
                const float* rp = &sS[cur][q][ty + dy][tx2];
                ull Ep[5];
#pragma unroll
                for (int m = 0; m < 5; m++) Ep[m] = *(const ull*)(rp + 2 * m);
                ull Om[4];
#pragma unroll
                for (int m = 0; m < 4; m++) Om[m] = mixp(Ep[m], Ep[m + 1]);
                ull* a = &acc[dy * 7];
                a[0] = fma2(f2, Om[0], a[0]);
                a[1] = fma2(f2, Ep[1], a[1]);
                a[2] = fma2(f2, Om[1], a[2]);
                a[3] = fma2(f2, Ep[2], a[3]);
                a[4] = fma2(f2, Om[2], a[4]);
                a[5] = fma2(f2, Ep[3], a[5]);
                a[6] = fma2(f2, Om[3], a[6]);
            }
        }
        __syncthreads();
    }
    float* ob = g_corr + LEAD + (size_t)b * 56 * PL1 + (y0 + ty + 1) * PSTR + x0 + tx2;
#pragma unroll
    for (int d = 0; d < 49; d++) {
        float lo, hi;
        unpack2(acc[d], lo, hi);
        lo *= (1.f / 96.f); hi *= (1.f / 96.f);
        lo = (lo >= 0.f) ? lo : 0.1f * lo;
        hi = (hi >= 0.f) ? hi : 0.1f * hi;
        *(float2*)&ob[(size_t)d * PL1] = make_float2(lo, hi);
    }
    // planes 49..55 are never written -> stay zero
}

// ---------------- weight duplication prep ----------------
// dst layout: [coBlk][cb][co16][ci8][9] of duplicated (w,w) 64-bit pairs
__global__ void dupw_k(const float* __restrict__ w, ull* __restrict__ dst,
                       int CO, int CIsrc, int CIpad) {
    int idx = blockIdx.x * 256 + threadIdx.x;
    int total = CO * CIpad * 9;
    if (idx >= total) return;
    int co = idx / (CIpad * 9);
    int r = idx % (CIpad * 9);
    int cip = r / 9, k = r % 9;
    float v = (cip < CIsrc) ? w[(co * CIsrc + cip) * 9 + k] : 0.f;
    unsigned u = __float_as_uint(v);
    int NB = CIpad / 8;
    dst[((co >> 4) * NB + (cip >> 3)) * 1152 + ((co & 15) * 8 + (cip & 7)) * 9 + k] =
        ((ull)u << 32) | (ull)u;
}

// ---------------- 4) conv3x3 + lrelu, cp.async double-buffered f32x2 ----------------
// Block: 32x x 16y x 16 co, 256 threads. Dynamic smem: 2 input buffers + 2 weight buffers.
template <int CI, int CO, int OH>   // OH = output halo (1 or 2)
__global__ __launch_bounds__(256, 2) void conv3_k(const float* __restrict__ in,
                                                  const ull* __restrict__ wd,
                                                  const float* __restrict__ bias,
                                                  float* __restrict__ out) {
    extern __shared__ __align__(16) float smem[];
    const int NB = CI / 8;
    float* sIn = smem;                       // [2][8][18][40]
    ull*   sW  = (ull*)(smem + 2 * 8 * 18 * 40);  // [2][1152]
    uint32_t sInB = (uint32_t)__cvta_generic_to_shared(sIn);
    uint32_t sWB  = (uint32_t)__cvta_generic_to_shared(sW);

    int tid = threadIdx.x;
    int lane = tid & 31, wrp = tid >> 5;
    int px = (lane & 3) * 8;      // 0,8,16,24
    int py = (lane >> 2) * 2;     // 0..14
    int coL = wrp * 2;

    int z = blockIdx.z;
    int b = z / (CO / 16);
    int coBlk = z % (CO / 16);
    int coBase = coBlk * 16;
    int x0 = blockIdx.x * 32, y0 = blockIdx.y * 16;

    const float* inb = in + (size_t)b * CI * PL1;
    const ull*   wdb = wd + (size_t)coBlk * NB * 1152;

    ull acc[2][2][4];
#pragma unroll
    for (int i = 0; i < 2; i++)
#pragma unroll
        for (int j = 0; j < 2; j++)
#pragma unroll
            for (int k = 0; k < 4; k++) acc[i][j][k] = 0ULL;

    auto issue = [&](int cb, int d) {
        for (int e = tid; e < 8 * 18 * 10; e += 256) {   // input: 1440 16B chunks
            int ci = e / 180, r = e % 180, ry = r / 10, cx = r % 10;
            uint32_t sd = sInB + (((d * 8 + ci) * 18 + ry) * 40 + cx * 4) * 4;
            cpa16(sd, inb + (size_t)(cb * 8 + ci) * PL1 + (y0 + ry) * PSTR + x0 - 4 + cx * 4);
        }
        const ull* ws = wdb + (size_t)cb * 1152;
        for (int e = tid; e < 576; e += 256) {           // weights: 576 16B chunks
            uint32_t sd = sWB + (d * 1152 + e * 2) * 8;
            cpa16(sd, ws + e * 2);
        }
        cpcommit();
    };

    issue(0, 0);
    for (int cb = 0; cb < NB; cb++) {
        int cur = cb & 1;
        if (cb + 1 < NB) { issue(cb + 1, cur ^ 1); cpwait<1>(); }
        else             { cpwait<0>(); }
        __syncthreads();
        const ull* sWc = sW + cur * 1152;
#pragma unroll
        for (int ci = 0; ci < 8; ci++) {
            ull w[2][9];
#pragma unroll
            for (int c2 = 0; c2 < 2; c2++)
#pragma unroll
                for (int k = 0; k < 9; k++)
                    w[c2][k] = sWc[((coL + c2) * 8 + ci) * 9 + k];
#pragma unroll
            for (int ri = 0; ri < 4; ri++) {
                const float* rp = &sIn[(((cur * 8 + ci) * 18) + py + ri) * 40 + px + 2];
                ull Ep[6];
#pragma unroll
                for (int m = 0; m < 6; m++) Ep[m] = *(const ull*)(rp + 2 * m);
                ull Em[5];
#pragma unroll
                for (int m = 0; m < 5; m++) Em[m] = mixp(Ep[m], Ep[m + 1]);
#pragma unroll
                for (int r2 = 0; r2 < 2; r2++) {
                    int ky = ri - r2;
                    if (ky < 0 || ky > 2) continue;
#pragma unroll
                    for (int c2 = 0; c2 < 2; c2++) {
                        ull w0 = w[c2][ky * 3 + 0];
                        ull w1_ = w[c2][ky * 3 + 1];
                        ull w2_ = w[c2][ky * 3 + 2];
#pragma unroll
                        for (int j = 0; j < 4; j++) {
                            ull a = acc[c2][r2][j];
                            a = fma2(w0, Em[j], a);       // kx=0
                            a = fma2(w1_, Ep[j + 1], a);  // kx=1
                            a = fma2(w2_, Em[j + 1], a);  // kx=2
                            acc[c2][r2][j] = a;
                        }
                    }
                }
            }
        }
        __syncthreads();
    }
    const int OPH = 128 + 2 * OH;
#pragma unroll
    for (int c2 = 0; c2 < 2; c2++) {
        int oc = coBase + coL + c2;
        float bv = bias[oc];
#pragma unroll
        for (int r2 = 0; r2 < 2; r2++) {
            int yy = y0 + py + r2;
#pragma unroll
            for (int j = 0; j < 4; j++) {
                float lo, hi;
                unpack2(acc[c2][r2][j], lo, hi);
                lo += bv; hi += bv;
                lo = (lo >= 0.f) ? lo : 0.1f * lo;
                hi = (hi >= 0.f) ? hi : 0.1f * hi;
                int xx = x0 + px + 2 * j;
                *(float2*)&out[(size_t)(b * CO + oc) * OPH * PSTR +
                               (yy + OH) * PSTR + xx] = make_float2(lo, hi);
            }
        }
    }
}

// ---------------- 5) conv5x5 (32->2) + flow add, padded input ----------------
__global__ __launch_bounds__(256) void conv5_k(const float* __restrict__ w4,
                                               const float* __restrict__ b4,
                                               float* __restrict__ out) {
    __shared__ float sIn[4][20][21];
    __shared__ float sW[1600];
    int tid = threadIdx.x;
    int tx = tid & 15, ty = tid >> 4;
    int x0 = blockIdx.x * 16, y0 = blockIdx.y * 16, b = blockIdx.z;
    const float* x3b = g_x3 + LEAD + (size_t)b * 32 * PL4;
    for (int e = tid; e < 1600; e += 256) sW[e] = w4[e];
    float a0 = 0.f, a1 = 0.f;
    for (int cb = 0; cb < 8; cb++) {
        __syncthreads();
        for (int e = tid; e < 4 * 20 * 20; e += 256) {
            int ci = e / 400, r = e % 400, ry = r / 20, rx = r % 20;
            sIn[ci][ry][rx] = x3b[(size_t)(cb * 4 + ci) * PL4 + (y0 + ry) * PSTR + x0 + rx - 2];
        }
        __syncthreads();
#pragma unroll
        for (int ci = 0; ci < 4; ci++) {
            int cig = cb * 4 + ci;
#pragma unroll
            for (int ky = 0; ky < 5; ky++)
#pragma unroll
                for (int kx = 0; kx < 5; kx++) {
                    float v = sIn[ci][ty + ky][tx + kx];
                    a0 += sW[cig * 25 + ky * 5 + kx] * v;
                    a1 += sW[(32 + cig) * 25 + ky * 5 + kx] * v;
                }
        }
    }
    int p = (y0 + ty) * Wn + x0 + tx;
    out[(b * 2 + 0) * HWn + p] = a0 + b4[0] + g_flow[(b * 2 + 0) * HWn + p];
    out[(b * 2 + 1) * HWn + p] = a1 + b4[1] + g_flow[(b * 2 + 1) * HWn + p];
}

// ---------------- launch ----------------
extern "C" void kernel_launch(void* const* d_in, const int* in_sizes, int n_in,
                              void* d_out, int out_size) {
    const float* featFirst  = (const float*)d_in[2];
    const float* featSecond = (const float*)d_in[3];
    const float* flowIn     = (const float*)d_in[4];
    const float* wu = (const float*)d_in[5];
    const float* w1 = (const float*)d_in[6];
    const float* b1 = (const float*)d_in[7];
    const float* w2 = (const float*)d_in[8];
    const float* b2 = (const float*)d_in[9];
    const float* w3 = (const float*)d_in[10];
    const float* b3 = (const float*)d_in[11];
    const float* w4 = (const float*)d_in[12];
    const float* b4 = (const float*)d_in[13];
    float* out = (float*)d_out;

    float *p_corr, *p_x1, *p_x2, *p_x3;
    ull *p_w1d, *p_w2d, *p_w3d;
    cudaGetSymbolAddress((void**)&p_corr, g_corr);
    cudaGetSymbolAddress((void**)&p_x1, g_x1);
    cudaGetSymbolAddress((void**)&p_x2, g_x2);
    cudaGetSymbolAddress((void**)&p_x3, g_x3);
    cudaGetSymbolAddress((void**)&p_w1d, g_w1d);
    cudaGetSymbolAddress((void**)&p_w2d, g_w2d);
    cudaGetSymbolAddress((void**)&p_w3d, g_w3d);

    const int SMEM = (2 * 8 * 18 * 40) * 4 + 2 * 1152 * 8;  // 64512 B
    cudaFuncSetAttribute(conv3_k<56, 128, 1>, cudaFuncAttributeMaxDynamicSharedMemorySize, SMEM);
    cudaFuncSetAttribute(conv3_k<128, 64, 1>, cudaFuncAttributeMaxDynamicSharedMemorySize, SMEM);
    cudaFuncSetAttribute(conv3_k<64, 32, 2>, cudaFuncAttributeMaxDynamicSharedMemorySize, SMEM);

    dupw_k<<<(128 * 56 * 9 + 255) / 256, 256>>>(w1, p_w1d, 128, 49, 56);
    dupw_k<<<(64 * 128 * 9 + 255) / 256, 256>>>(w2, p_w2d, 64, 128, 128);
    dupw_k<<<(32 * 64 * 9 + 255) / 256, 256>>>(w3, p_w3d, 32, 64, 64);
    upflow_k<<<(Bn * 2 * HWn) / 256, 256>>>(flowIn, wu);
    warp_k<<<dim3(Hn, Bn), Wn>>>(featSecond);
    corr_k<<<dim3(4, 8, Bn), 256>>>(featFirst);
    conv3_k<56, 128, 1><<<dim3(4, 8, Bn * 8), 256, SMEM>>>(p_corr + LEAD, p_w1d, b1, p_x1 + LEAD);
    conv3_k<128, 64, 1><<<dim3(4, 8, Bn * 4), 256, SMEM>>>(p_x1 + LEAD, p_w2d, b2, p_x2 + LEAD);
    conv3_k<64, 32, 2><<<dim3(4, 8, Bn * 2), 256, SMEM>>>(p_x2 + LEAD, p_w3d, b3, p_x3 + LEAD);
    conv5_k<<<dim3(8, 8, Bn), 256>>>(w4, b4, out);
}

// round 13
// speedup vs baseline: 1.4138x; 1.0320x over previous
#include <cuda_runtime.h>
#include <math.h>
#include <stdint.h>

// Problem constants
#define Bn 16
#define Cn 96
#define Hn 128
#define Wn 128
#define HWn (Hn*Wn)

#define PSTR 136              // padded row stride (floats)
#define PH1 130               // halo-1 plane rows
#define PH2 134               // halo-3 plane rows (feat2)
#define PH4 132               // halo-2 plane rows (x3)
#define PL1 (PH1*PSTR)
#define PL2 (PH2*PSTR)
#define PL4 (PH4*PSTR)
#define LEAD 64               // leading zero pad (floats) so col -4 reads are in-bounds

typedef unsigned long long ull;

// ---------------- scratch (static device arrays; zero-initialized -> borders stay 0) ----
__device__ float g_flow [Bn*2*HWn];
__device__ float g_feat2[LEAD + Bn*Cn*PL2];       // warped features, halo 3
__device__ float g_corr [LEAD + Bn*56*PL1];       // lrelu(corr), 49 used + 7 zero planes, halo 1
__device__ float g_x1   [LEAD + Bn*128*PL1];
__device__ float g_x2   [LEAD + Bn*64*PL1];
__device__ float g_x3   [LEAD + Bn*32*PL4];       // halo 2
__device__ ull   g_w1d  [8*7*1152];               // duplicated weight pairs
__device__ ull   g_w2d  [4*16*1152];
__device__ ull   g_w3d  [2*8*1152];

// ---------------- f32x2 helpers ----------------
__device__ __forceinline__ void unpack2(ull v, float& lo, float& hi) {
    unsigned a, b;
    asm("mov.b64 {%0, %1}, %2;" : "=r"(a), "=r"(b) : "l"(v));
    lo = __uint_as_float(a); hi = __uint_as_float(b);
}
__device__ __forceinline__ ull fma2(ull a, ull b, ull c) {
    ull d;
    asm("fma.rn.f32x2 %0, %1, %2, %3;" : "=l"(d) : "l"(a), "l"(b), "l"(c));
    return d;
}
__device__ __forceinline__ ull mixp(ull a, ull b) {  // (a.hi, b.lo)
    ull r;
    asm("{\n\t.reg .b32 al, ah, bl, bh;\n\t"
        "mov.b64 {al, ah}, %1;\n\tmov.b64 {bl, bh}, %2;\n\t"
        "mov.b64 %0, {ah, bl};\n\t}" : "=l"(r) : "l"(a), "l"(b));
    return r;
}
// ---------------- cp.async helpers ----------------
__device__ __forceinline__ void cpa16(uint32_t sdst, const void* gsrc) {
    asm volatile("{\n\t.reg .u64 g;\n\tcvta.to.global.u64 g, %1;\n\t"
                 "cp.async.cg.shared.global [%0], [g], 16;\n\t}"
                 :: "r"(sdst), "l"(gsrc) : "memory");
}
__device__ __forceinline__ void cpcommit() { asm volatile("cp.async.commit_group;" ::: "memory"); }
template <int N>
__device__ __forceinline__ void cpwait() { asm volatile("cp.async.wait_group %0;" :: "n"(N) : "memory"); }

// ---------------- 1) upflow ----------------
__global__ void upflow_k(const float* __restrict__ flowIn, const float* __restrict__ wu) {
    int idx = blockIdx.x * 256 + threadIdx.x;
    int x = idx & 127, y = (idx >> 7) & 127, c = (idx >> 14) & 1, b = idx >> 15;
    float acc = 0.f;
#pragma unroll
    for (int ky = 0; ky < 4; ky++) {
        int tyy = y + ky - 2;
        if (tyy & 1) continue;
        int iy = tyy >> 1;
        if (iy < 0 || iy >= 64) continue;
#pragma unroll
        for (int kx = 0; kx < 4; kx++) {
            int txx = x + kx - 2;
            if (txx & 1) continue;
            int ix = txx >> 1;
            if (ix < 0 || ix >= 64) continue;
            acc += wu[c * 16 + (3 - ky) * 4 + (3 - kx)] *
                   flowIn[((b * 2 + c) * 64 + iy) * 64 + ix];
        }
    }
    g_flow[idx] = acc;
}

// ---------------- 2) backward warp -> padded g_feat2 ----------------
__global__ void warp_k(const float* __restrict__ feat) {
    int x = threadIdx.x, y = blockIdx.x, b = blockIdx.y;
    int pp = y * Wn + x;
    float sx = (float)x + 2.5f * g_flow[(b * 2 + 0) * HWn + pp];
    float sy = (float)y + 2.5f * g_flow[(b * 2 + 1) * HWn + pp];
    float x0f = floorf(sx), y0f = floorf(sy);
    float ax = sx - x0f, ay = sy - y0f;
    int ix0 = (int)x0f, iy0 = (int)y0f;
    int ix1 = ix0 + 1, iy1 = iy0 + 1;
    bool vx0 = (ix0 >= 0) && (ix0 < Wn), vx1 = (ix1 >= 0) && (ix1 < Wn);
    bool vy0 = (iy0 >= 0) && (iy0 < Hn), vy1 = (iy1 >= 0) && (iy1 < Hn);
    float wa = (1.f - ax) * (1.f - ay), wb = ax * (1.f - ay);
    float wc = (1.f - ax) * ay,         wd = ax * ay;
    bool va = vx0 && vy0, vb = vx1 && vy0, vc = vx0 && vy1, vd = vx1 && vy1;
    float alpha = (va ? wa : 0.f) + (vb ? wb : 0.f) + (vc ? wc : 0.f) + (vd ? wd : 0.f);
    float* outb = g_feat2 + LEAD + (size_t)b * Cn * PL2 + (y + 3) * PSTR + x;
    if (alpha > 0.999f) {
        const float* inb = feat + (size_t)b * Cn * HWn;
        int oa = iy0 * Wn + ix0, ob = iy0 * Wn + ix1;
        int oc_ = iy1 * Wn + ix0, od = iy1 * Wn + ix1;
#pragma unroll 4
        for (int c = 0; c < Cn; c++) {
            const float* pl = inb + c * HWn;
            float v = 0.f;
            if (va) v += wa * __ldg(pl + oa);
            if (vb) v += wb * __ldg(pl + ob);
            if (vc) v += wc * __ldg(pl + oc_);
            if (vd) v += wd * __ldg(pl + od);
            outb[(size_t)c * PL2] = v;
        }
    } else {
        for (int c = 0; c < Cn; c++) outb[(size_t)c * PL2] = 0.f;
    }
}

// ---------------- 3) correlation + lrelu, cp.async double-buffered ----------------
__global__ __launch_bounds__(256) void corr_k(const float* __restrict__ first) {
    __shared__ __align__(16) float sS[2][4][22][40];
    int tid = threadIdx.x;
    int tx2 = (tid & 15) * 2;     // 0..30
    int ty  = tid >> 4;           // 0..15
    int x0 = blockIdx.x * 32, y0 = blockIdx.y * 16, b = blockIdx.z;
    ull acc[49];
#pragma unroll
    for (int d = 0; d < 49; d++) acc[d] = 0ULL;
    const float* fb  = first + (size_t)b * Cn * HWn;
    const float* sb  = g_feat2 + LEAD + (size_t)b * Cn * PL2;
    uint32_t sbase = (uint32_t)__cvta_generic_to_shared(&sS[0][0][0][0]);

    auto issue = [&](int cb, int d) {
        for (int e = tid; e < 4 * 22 * 10; e += 256) {
            int q = e / 220, r = e % 220, ry = r / 10, cx = r % 10;
            uint32_t sd = sbase + (((d * 4 + q) * 22 + ry) * 40 + cx * 4) * 4;
            cpa16(sd, sb + (size_t)(cb * 4 + q) * PL2 + (y0 + ry) * PSTR + x0 - 4 + cx * 4);
        }
        cpcommit();
    };
    issue(0, 0);
    for (int cb = 0; cb < 24; cb++) {
        int cur = cb & 1;
        if (cb + 1 < 24) { issue(cb + 1, cur ^ 1); cpwait<1>(); }
        else             { cpwait<0>(); }
        __syncthreads();
#pragma unroll
        for (int q = 0; q < 4; q++) {
            ull f2 = *(const ull*)&fb[(cb * 4 + q) * HWn + (y0 + ty) * Wn + x0 + tx2];
#pragma unroll
            for (int dy = 0; dy < 7; dy++) {
                const float* rp = &sS[cur][q][ty + dy][tx2];
                ull Ep[5];
#pragma unroll
                for (int m = 0; m < 5; m++) Ep[m] = *(const ull*)(rp + 2 * m);
                ull Om[4];
#pragma unroll
                for (int m = 0; m < 4; m++) Om[m] = mixp(Ep[m], Ep[m + 1]);
                ull* a = &acc[dy * 7];
                a[0] = fma2(f2, Om[0], a[0]);
                a[1] = fma2(f2, Ep[1], a[1]);
                a[2] = fma2(f2, Om[1], a[2]);
                a[3] = fma2(f2, Ep[2], a[3]);
                a[4] = fma2(f2, Om[2], a[4]);
                a[5] = fma2(f2, Ep[3], a[5]);
                a[6] = fma2(f2, Om[3], a[6]);
            }
        }
        __syncthreads();
    }
    float* ob = g_corr + LEAD + (size_t)b * 56 * PL1 + (y0 + ty + 1) * PSTR + x0 + tx2;
#pragma unroll
    for (int d = 0; d < 49; d++) {
        float lo, hi;
        unpack2(acc[d], lo, hi);
        lo *= (1.f / 96.f); hi *= (1.f / 96.f);
        lo = (lo >= 0.f) ? lo : 0.1f * lo;
        hi = (hi >= 0.f) ? hi : 0.1f * hi;
        *(float2*)&ob[(size_t)d * PL1] = make_float2(lo, hi);
    }
}

// ---------------- weight duplication prep ----------------
__global__ void dupw_k(const float* __restrict__ w, ull* __restrict__ dst,
                       int CO, int CIsrc, int CIpad) {
    int idx = blockIdx.x * 256 + threadIdx.x;
    int total = CO * CIpad * 9;
    if (idx >= total) return;
    int co = idx / (CIpad * 9);
    int r = idx % (CIpad * 9);
    int cip = r / 9, k = r % 9;
    float v = (cip < CIsrc) ? w[(co * CIsrc + cip) * 9 + k] : 0.f;
    unsigned u = __float_as_uint(v);
    int NB = CIpad / 8;
    dst[((co >> 4) * NB + (cip >> 3)) * 1152 + ((co & 15) * 8 + (cip & 7)) * 9 + k] =
        ((ull)u << 32) | (ull)u;
}

// ---------------- 4) conv3x3 + lrelu, cp.async double-buffered f32x2 ----------------
// Block: 32x x 16y x 16 co, 256 threads.
// Warp composition (bank-conflict fix): lane = xg(2b) | yg(1b) | cq(2b)
//   -> warp spans 4 x-groups x 2 y-groups x 4 co-quads: input LDS.64 has only
//      8 unique addresses (co-lanes broadcast-dedup) -> ~2 crossbar cycles, not 8-way.
// Warp id: w&3 -> y-quad (4 rows), w>>2 -> co-octet (8 co).
template <int CI, int CO, int OH>   // OH = output halo (1 or 2)
__global__ __launch_bounds__(256, 2) void conv3_k(const float* __restrict__ in,
                                                  const ull* __restrict__ wd,
                                                  const float* __restrict__ bias,
                                                  float* __restrict__ out) {
    extern __shared__ __align__(16) float smem[];
    const int NB = CI / 8;
    float* sIn = smem;                       // [2][8][18][40]
    ull*   sW  = (ull*)(smem + 2 * 8 * 18 * 40);  // [2][1152]
    uint32_t sInB = (uint32_t)__cvta_generic_to_shared(sIn);
    uint32_t sWB  = (uint32_t)__cvta_generic_to_shared(sW);

    int tid = threadIdx.x;
    int lane = tid & 31, wrp = tid >> 5;
    int px  = (lane & 3) * 8;                         // 0,8,16,24
    int py  = (wrp & 3) * 4 + ((lane >> 2) & 1) * 2;  // 0..14 step 2
    int coL = (wrp >> 2) * 8 + (lane >> 3) * 2;       // 0..14 step 2

    int z = blockIdx.z;
    int b = z / (CO / 16);
    int coBlk = z % (CO / 16);
    int coBase = coBlk * 16;
    int x0 = blockIdx.x * 32, y0 = blockIdx.y * 16;

    const float* inb = in + (size_t)b * CI * PL1;
    const ull*   wdb = wd + (size_t)coBlk * NB * 1152;

    ull acc[2][2][4];
#pragma unroll
    for (int i = 0; i < 2; i++)
#pragma unroll
        for (int j = 0; j < 2; j++)
#pragma unroll
            for (int k = 0; k < 4; k++) acc[i][j][k] = 0ULL;

    auto issue = [&](int cb, int d) {
        for (int e = tid; e < 8 * 18 * 10; e += 256) {   // input: 1440 16B chunks
            int ci = e / 180, r = e % 180, ry = r / 10, cx = r % 10;
            uint32_t sd = sInB + (((d * 8 + ci) * 18 + ry) * 40 + cx * 4) * 4;
            cpa16(sd, inb + (size_t)(cb * 8 + ci) * PL1 + (y0 + ry) * PSTR + x0 - 4 + cx * 4);
        }
        const ull* ws = wdb + (size_t)cb * 1152;
        for (int e = tid; e < 576; e += 256) {           // weights: 576 16B chunks
            uint32_t sd = sWB + (d * 1152 + e * 2) * 8;
            cpa16(sd, ws + e * 2);
        }
        cpcommit();
    };

    issue(0, 0);
    for (int cb = 0; cb < NB; cb++) {
        int cur = cb & 1;
        if (cb + 1 < NB) { issue(cb + 1, cur ^ 1); cpwait<1>(); }
        else             { cpwait<0>(); }
        __syncthreads();
        const ull* sWc = sW + cur * 1152;
#pragma unroll
        for (int ci = 0; ci < 8; ci++) {
            ull w[2][9];
#pragma unroll
            for (int c2 = 0; c2 < 2; c2++)
#pragma unroll
                for (int k = 0; k < 9; k++)
                    w[c2][k] = sWc[((coL + c2) * 8 + ci) * 9 + k];
#pragma unroll
            for (int ri = 0; ri < 4; ri++) {
                const float* rp = &sIn[(((cur * 8 + ci) * 18) + py + ri) * 40 + px + 2];
                ull Ep[6];
#pragma unroll
                for (int m = 0; m < 6; m++) Ep[m] = *(const ull*)(rp + 2 * m);
                ull Em[5];
#pragma unroll
                for (int m = 0; m < 5; m++) Em[m] = mixp(Ep[m], Ep[m + 1]);
#pragma unroll
                for (int r2 = 0; r2 < 2; r2++) {
                    int ky = ri - r2;
                    if (ky < 0 || ky > 2) continue;
#pragma unroll
                    for (int c2 = 0; c2 < 2; c2++) {
                        ull w0 = w[c2][ky * 3 + 0];
                        ull w1_ = w[c2][ky * 3 + 1];
                        ull w2_ = w[c2][ky * 3 + 2];
#pragma unroll
                        for (int j = 0; j < 4; j++) {
                            ull a = acc[c2][r2][j];
                            a = fma2(w0, Em[j], a);       // kx=0
                            a = fma2(w1_, Ep[j + 1], a);  // kx=1
                            a = fma2(w2_, Em[j + 1], a);  // kx=2
                            acc[c2][r2][j] = a;
                        }
                    }
                }
            }
        }
        __syncthreads();
    }
    const int OPH = 128 + 2 * OH;
#pragma unroll
    for (int c2 = 0; c2 < 2; c2++) {
        int oc = coBase + coL + c2;
        float bv = bias[oc];
#pragma unroll
        for (int r2 = 0; r2 < 2; r2++) {
            int yy = y0 + py + r2;
#pragma unroll
            for (int j = 0; j < 4; j++) {
                float lo, hi;
                unpack2(acc[c2][r2][j], lo, hi);
                lo += bv; hi += bv;
                lo = (lo >= 0.f) ? lo : 0.1f * lo;
                hi = (hi >= 0.f) ? hi : 0.1f * hi;
                int xx = x0 + px + 2 * j;
                *(float2*)&out[(size_t)(b * CO + oc) * OPH * PSTR +
                               (yy + OH) * PSTR + xx] = make_float2(lo, hi);
            }
        }
    }
}

// ---------------- 5) conv5x5 (32->2) + flow add, padded input ----------------
__global__ __launch_bounds__(256) void conv5_k(const float* __restrict__ w4,
                                               const float* __restrict__ b4,
                                               float* __restrict__ out) {
    __shared__ float sIn[4][20][21];
    __shared__ float sW[1600];
    int tid = threadIdx.x;
    int tx = tid & 15, ty = tid >> 4;
    int x0 = blockIdx.x * 16, y0 = blockIdx.y * 16, b = blockIdx.z;
    const float* x3b = g_x3 + LEAD + (size_t)b * 32 * PL4;
    for (int e = tid; e < 1600; e += 256) sW[e] = w4[e];
    float a0 = 0.f, a1 = 0.f;
    for (int cb = 0; cb < 8; cb++) {
        __syncthreads();
        for (int e = tid; e < 4 * 20 * 20; e += 256) {
            int ci = e / 400, r = e % 400, ry = r / 20, rx = r % 20;
            sIn[ci][ry][rx] = x3b[(size_t)(cb * 4 + ci) * PL4 + (y0 + ry) * PSTR + x0 + rx - 2];
        }
        __syncthreads();
#pragma unroll
        for (int ci = 0; ci < 4; ci++) {
            int cig = cb * 4 + ci;
#pragma unroll
            for (int ky = 0; ky < 5; ky++)
#pragma unroll
                for (int kx = 0; kx < 5; kx++) {
                    float v = sIn[ci][ty + ky][tx + kx];
                    a0 += sW[cig * 25 + ky * 5 + kx] * v;
                    a1 += sW[(32 + cig) * 25 + ky * 5 + kx] * v;
                }
        }
    }
    int p = (y0 + ty) * Wn + x0 + tx;
    out[(b * 2 + 0) * HWn + p] = a0 + b4[0] + g_flow[(b * 2 + 0) * HWn + p];
    out[(b * 2 + 1) * HWn + p] = a1 + b4[1] + g_flow[(b * 2 + 1) * HWn + p];
}

// ---------------- launch ----------------
extern "C" void kernel_launch(void* const* d_in, const int* in_sizes, int n_in,
                              void* d_out, int out_size) {
    const float* featFirst  = (const float*)d_in[2];
    const float* featSecond = (const float*)d_in[3];
    const float* flowIn     = (const float*)d_in[4];
    const float* wu = (const float*)d_in[5];
    const float* w1 = (const float*)d_in[6];
    const float* b1 = (const float*)d_in[7];
    const float* w2 = (const float*)d_in[8];
    const float* b2 = (const float*)d_in[9];
    const float* w3 = (const float*)d_in[10];
    const float* b3 = (const float*)d_in[11];
    const float* w4 = (const float*)d_in[12];
    const float* b4 = (const float*)d_in[13];
    float* out = (float*)d_out;

    float *p_corr, *p_x1, *p_x2, *p_x3;
    ull *p_w1d, *p_w2d, *p_w3d;
    cudaGetSymbolAddress((void**)&p_corr, g_corr);
    cudaGetSymbolAddress((void**)&p_x1, g_x1);
    cudaGetSymbolAddress((void**)&p_x2, g_x2);
    cudaGetSymbolAddress((void**)&p_x3, g_x3);
    cudaGetSymbolAddress((void**)&p_w1d, g_w1d);
    cudaGetSymbolAddress((void**)&p_w2d, g_w2d);
    cudaGetSymbolAddress((void**)&p_w3d, g_w3d);

    const int SMEM = (2 * 8 * 18 * 40) * 4 + 2 * 1152 * 8;  // 64512 B
    cudaFuncSetAttribute(conv3_k<56, 128, 1>, cudaFuncAttributeMaxDynamicSharedMemorySize, SMEM);
    cudaFuncSetAttribute(conv3_k<128, 64, 1>, cudaFuncAttributeMaxDynamicSharedMemorySize, SMEM);
    cudaFuncSetAttribute(conv3_k<64, 32, 2>, cudaFuncAttributeMaxDynamicSharedMemorySize, SMEM);

    dupw_k<<<(128 * 56 * 9 + 255) / 256, 256>>>(w1, p_w1d, 128, 49, 56);
    dupw_k<<<(64 * 128 * 9 + 255) / 256, 256>>>(w2, p_w2d, 64, 128, 128);
    dupw_k<<<(32 * 64 * 9 + 255) / 256, 256>>>(w3, p_w3d, 32, 64, 64);
    upflow_k<<<(Bn * 2 * HWn) / 256, 256>>>(flowIn, wu);
    warp_k<<<dim3(Hn, Bn), Wn>>>(featSecond);
    corr_k<<<dim3(4, 8, Bn), 256>>>(featFirst);
    conv3_k<56, 128, 1><<<dim3(4, 8, Bn * 8), 256, SMEM>>>(p_corr + LEAD, p_w1d, b1, p_x1 + LEAD);
    conv3_k<128, 64, 1><<<dim3(4, 8, Bn * 4), 256, SMEM>>>(p_x1 + LEAD, p_w2d, b2, p_x2 + LEAD);
    conv3_k<64, 32, 2><<<dim3(4, 8, Bn * 2), 256, SMEM>>>(p_x2 + LEAD, p_w3d, b3, p_x3 + LEAD);
    conv5_k<<<dim3(8, 8, Bn), 256>>>(w4, b4, out);
}